// round 1
// baseline (speedup 1.0000x reference)
#include <cuda_runtime.h>

#define NN 100000
#define NE 3200000
#define DF 512
#define HID 16
#define NC  40
#define SCAN_CHUNK 1024
#define NB ((NN + SCAN_CHUNK - 1) / SCAN_CHUNK)   // 98

// ---------------- device scratch (no runtime allocation allowed) ----------------
__device__ float g_dinv[NN];        // degree, then d^-1/2
__device__ int   g_cnt[NN];         // in-degree (edges only)
__device__ int   g_ptr[NN];         // CSR offsets (exclusive scan of g_cnt)
__device__ int   g_cur[NN];         // scatter cursors
__device__ int   g_src[NE];         // source node per CSR slot
__device__ float g_nrm[NE];         // edge norm per CSR slot
__device__ float g_hx [NN * HID];   // x @ W1
__device__ float g_h1 [NN * HID];   // relu(agg1 + b1)
__device__ float g_ag2[NN * HID];   // agg of h1 (pre-W2)
__device__ int   g_part[NB];

// ---------------- init: self-loop degree = 1, zero counters ----------------
__global__ void k_init(int n) {
    int i = blockIdx.x * blockDim.x + threadIdx.x;
    if (i < n) { g_dinv[i] = 1.0f; g_cnt[i] = 0; g_cur[i] = 0; }
}

// ---------------- pass 1: degree accumulation + in-degree histogram ----------------
__global__ void k_pass1(const int* __restrict__ col, const float* __restrict__ w, int E) {
    int e = blockIdx.x * blockDim.x + threadIdx.x;
    if (e < E) {
        int c = col[e];
        atomicAdd(&g_dinv[c], w[e]);
        atomicAdd(&g_cnt[c], 1);
    }
}

__global__ void k_rsqrt(int n) {
    int i = blockIdx.x * blockDim.x + threadIdx.x;
    if (i < n) g_dinv[i] = rsqrtf(g_dinv[i]);   // deg >= 1 always (self loop)
}

// ---------------- 3-kernel exclusive scan of g_cnt -> g_ptr ----------------
__global__ void k_scanA(int n) {
    __shared__ int sh[256];
    int t = threadIdx.x;
    int base = blockIdx.x * SCAN_CHUNK;
    int s = 0;
    #pragma unroll
    for (int k = 0; k < 4; k++) {
        int idx = base + t + k * 256;
        if (idx < n) s += g_cnt[idx];
    }
    sh[t] = s;
    __syncthreads();
    for (int off = 128; off > 0; off >>= 1) {
        if (t < off) sh[t] += sh[t + off];
        __syncthreads();
    }
    if (t == 0) g_part[blockIdx.x] = sh[0];
}

__global__ void k_scanB() {
    __shared__ int s[128];
    int t = threadIdx.x;
    int v = (t < NB) ? g_part[t] : 0;
    s[t] = v;
    __syncthreads();
    #pragma unroll
    for (int off = 1; off < 128; off <<= 1) {
        int a = (t >= off) ? s[t - off] : 0;
        __syncthreads();
        s[t] += a;
        __syncthreads();
    }
    if (t < NB) g_part[t] = s[t] - v;   // exclusive
}

__global__ void k_scanC(int n) {
    __shared__ int s[SCAN_CHUNK];
    int t = threadIdx.x;
    int idx = blockIdx.x * SCAN_CHUNK + t;
    int v = (idx < n) ? g_cnt[idx] : 0;
    s[t] = v;
    __syncthreads();
    for (int off = 1; off < SCAN_CHUNK; off <<= 1) {
        int a = (t >= off) ? s[t - off] : 0;
        __syncthreads();
        s[t] += a;
        __syncthreads();
    }
    if (idx < n) g_ptr[idx] = g_part[blockIdx.x] + s[t] - v;   // exclusive prefix
}

// ---------------- CSR build: scatter (src, norm) sorted by destination ----------------
__global__ void k_build(const int* __restrict__ row, const int* __restrict__ col,
                        const float* __restrict__ w, int E) {
    int e = blockIdx.x * blockDim.x + threadIdx.x;
    if (e < E) {
        int r = row[e];
        int c = col[e];
        float nv = g_dinv[r] * w[e] * g_dinv[c];
        int pos = g_ptr[c] + atomicAdd(&g_cur[c], 1);
        g_src[pos] = r;
        g_nrm[pos] = nv;
    }
}

// ---------------- GEMM1: g_hx = x @ W1   (100K x 512 @ 512 x 16) ----------------
// 128 rows per block; W1 in shared (broadcast reads), x tiled 16 cols, conflict-free.
__global__ void __launch_bounds__(128) k_gemm1(const float* __restrict__ x,
                                               const float* __restrict__ W1, int n) {
    __shared__ float Ws[DF * HID];       // 32 KB
    __shared__ float xs[128][17];        // 8.5 KB, padded
    int t = threadIdx.x;
    int row = blockIdx.x * 128 + t;

    for (int i = t; i < DF * HID; i += 128) Ws[i] = W1[i];

    float acc[16];
    #pragma unroll
    for (int h = 0; h < 16; h++) acc[h] = 0.0f;

    for (int jb = 0; jb < DF; jb += 16) {
        __syncthreads();
        // load 128 rows x 16 cols; flat f = i*128 + t -> warp covers 2 rows x 16 cols (64B coalesced)
        #pragma unroll
        for (int i = 0; i < 16; i++) {
            int f = i * 128 + t;
            int r = f >> 4, c = f & 15;
            int gr = blockIdx.x * 128 + r;
            xs[r][c] = (gr < n) ? x[gr * DF + jb + c] : 0.0f;
        }
        __syncthreads();
        if (row < n) {
            #pragma unroll
            for (int c = 0; c < 16; c++) {
                float xv = xs[t][c];
                const float4* wp = (const float4*)&Ws[(jb + c) * HID];
                float4 w0 = wp[0], w1 = wp[1], w2 = wp[2], w3 = wp[3];
                acc[0]  += xv * w0.x; acc[1]  += xv * w0.y; acc[2]  += xv * w0.z; acc[3]  += xv * w0.w;
                acc[4]  += xv * w1.x; acc[5]  += xv * w1.y; acc[6]  += xv * w1.z; acc[7]  += xv * w1.w;
                acc[8]  += xv * w2.x; acc[9]  += xv * w2.y; acc[10] += xv * w2.z; acc[11] += xv * w2.w;
                acc[12] += xv * w3.x; acc[13] += xv * w3.y; acc[14] += xv * w3.z; acc[15] += xv * w3.w;
            }
        }
    }
    if (row < n) {
        float4* o = (float4*)&g_hx[row * HID];
        o[0] = make_float4(acc[0],  acc[1],  acc[2],  acc[3]);
        o[1] = make_float4(acc[4],  acc[5],  acc[6],  acc[7]);
        o[2] = make_float4(acc[8],  acc[9],  acc[10], acc[11]);
        o[3] = make_float4(acc[12], acc[13], acc[14], acc[15]);
    }
}

// ---------------- aggregation: warp per destination node, CSR gather ----------------
// PHASE 1: in = g_hx, out = g_h1, apply +b1 and ReLU.
// PHASE 2: in = g_h1, out = g_ag2, raw accumulation.
template <int PHASE>
__global__ void k_agg(const float* __restrict__ bias, int n) {
    const float4* in = (PHASE == 1) ? (const float4*)g_hx : (const float4*)g_h1;
    float4* out      = (PHASE == 1) ? (float4*)g_h1       : (float4*)g_ag2;

    int node = (blockIdx.x * blockDim.x + threadIdx.x) >> 5;
    int lane = threadIdx.x & 31;
    if (node >= n) return;

    int q  = lane & 3;    // float4 slot (dims 4q..4q+3)
    int es = lane >> 2;   // edge slot 0..7
    int start = g_ptr[node];
    int end   = start + g_cnt[node];

    float4 acc = make_float4(0.f, 0.f, 0.f, 0.f);
    for (int e = start + es; e < end; e += 8) {
        int   src = g_src[e];
        float nv  = g_nrm[e];
        float4 v  = in[src * 4 + q];
        acc.x += nv * v.x; acc.y += nv * v.y; acc.z += nv * v.z; acc.w += nv * v.w;
    }
    // reduce across the 8 edge slots (lanes q, q+4, ..., q+28)
    #pragma unroll
    for (int off = 4; off < 32; off <<= 1) {
        acc.x += __shfl_down_sync(0xffffffffu, acc.x, off);
        acc.y += __shfl_down_sync(0xffffffffu, acc.y, off);
        acc.z += __shfl_down_sync(0xffffffffu, acc.z, off);
        acc.w += __shfl_down_sync(0xffffffffu, acc.w, off);
    }
    if (lane < 4) {
        float d  = g_dinv[node];
        float d2 = d * d;                       // self-loop norm (w = 1)
        float4 sv = in[node * 4 + lane];
        acc.x += d2 * sv.x; acc.y += d2 * sv.y; acc.z += d2 * sv.z; acc.w += d2 * sv.w;
        if (PHASE == 1) {
            float4 b = ((const float4*)bias)[lane];
            acc.x = fmaxf(acc.x + b.x, 0.f);
            acc.y = fmaxf(acc.y + b.y, 0.f);
            acc.z = fmaxf(acc.z + b.z, 0.f);
            acc.w = fmaxf(acc.w + b.w, 0.f);
        }
        out[node * 4 + lane] = acc;
    }
}

// ---------------- final: out = g_ag2 @ W2 + b2   (100K x 16 @ 16 x 40) ----------------
__global__ void k_out(float* __restrict__ out, const float* __restrict__ W2,
                      const float* __restrict__ b2, int n) {
    int idx = blockIdx.x * blockDim.x + threadIdx.x;
    int total = n * NC;
    if (idx >= total) return;
    int node = idx / NC;
    int cls  = idx - node * NC;
    float s = b2[cls];
    const float* a = &g_ag2[node * HID];
    #pragma unroll
    for (int h = 0; h < HID; h++) s += a[h] * W2[h * NC + cls];
    out[idx] = s;
}

// ---------------- launch ----------------
extern "C" void kernel_launch(void* const* d_in, const int* in_sizes, int n_in,
                              void* d_out, int out_size) {
    const float* x  = (const float*)d_in[0];
    const int*   ei = (const int*)  d_in[1];
    const float* ew = (const float*)d_in[2];
    const float* W1 = (const float*)d_in[3];
    const float* b1 = (const float*)d_in[4];
    const float* W2 = (const float*)d_in[5];
    const float* b2 = (const float*)d_in[6];

    int E = in_sizes[2];              // edge_weight count
    int n = in_sizes[0] / DF;         // node count
    const int* rowp = ei;             // edge_index[0]
    const int* colp = ei + E;         // edge_index[1]

    int nb256  = (n + 255) / 256;
    int eb256  = (E + 255) / 256;

    k_init  <<<nb256, 256>>>(n);
    k_pass1 <<<eb256, 256>>>(colp, ew, E);
    k_rsqrt <<<nb256, 256>>>(n);
    k_scanA <<<NB, 256>>>(n);
    k_scanB <<<1, 128>>>();
    k_scanC <<<NB, SCAN_CHUNK>>>(n);
    k_build <<<eb256, 256>>>(rowp, colp, ew, E);

    k_gemm1 <<<(n + 127) / 128, 128>>>(x, W1, n);

    long wthreads = (long)n * 32;
    int aggblocks = (int)((wthreads + 255) / 256);
    k_agg<1><<<aggblocks, 256>>>(b1, n);
    k_agg<2><<<aggblocks, 256>>>(nullptr, n);

    int total = n * NC;
    k_out<<<(total + 255) / 256, 256>>>((float*)d_out, W2, b2, n);
}

// round 2
// speedup vs baseline: 1.0059x; 1.0059x over previous
#include <cuda_runtime.h>

#define NN 100000
#define NE 3200000
#define DF 512
#define HID 16
#define NC  40
#define SCAN_CHUNK 1024
#define NB ((NN + SCAN_CHUNK - 1) / SCAN_CHUNK)   // 98

// ---------------- device scratch ----------------
__device__ float g_dinv[NN];        // degree, then d^-1/2
__device__ int   g_cnt[NN];         // in-degree (edges only)
__device__ int   g_ptr[NN];         // CSR offsets
__device__ int   g_cur[NN];         // scatter cursors
__device__ int2  g_edge[NE];        // (src, norm-as-int) per CSR slot
__device__ float g_hx [NN * HID];   // x @ W1
__device__ float g_h1 [NN * HID];   // relu(agg1 + b1)
__device__ int   g_part[NB];

#define FMA2(d, a, b) asm("fma.rn.f32x2 %0, %1, %2, %0;" : "+l"(d) : "l"(a), "l"(b))

// ---------------- init ----------------
__global__ void k_init(int n) {
    int i = blockIdx.x * blockDim.x + threadIdx.x;
    if (i < n) { g_dinv[i] = 1.0f; g_cnt[i] = 0; g_cur[i] = 0; }
}

// ---------------- pass 1: weighted degree + in-degree histogram ----------------
__global__ void k_pass1(const int* __restrict__ col, const float* __restrict__ w, int E) {
    int e = blockIdx.x * blockDim.x + threadIdx.x;
    if (e < E) {
        int c = col[e];
        atomicAdd(&g_dinv[c], w[e]);
        atomicAdd(&g_cnt[c], 1);
    }
}

// ---------------- scan stage A (block sums) + fused rsqrt ----------------
__global__ void k_scanA(int n) {
    __shared__ int sh[256];
    int t = threadIdx.x;
    int base = blockIdx.x * SCAN_CHUNK;
    int s = 0;
    #pragma unroll
    for (int k = 0; k < 4; k++) {
        int idx = base + t + k * 256;
        if (idx < n) {
            s += g_cnt[idx];
            g_dinv[idx] = rsqrtf(g_dinv[idx]);   // deg >= 1 (self loop)
        }
    }
    sh[t] = s;
    __syncthreads();
    for (int off = 128; off > 0; off >>= 1) {
        if (t < off) sh[t] += sh[t + off];
        __syncthreads();
    }
    if (t == 0) g_part[blockIdx.x] = sh[0];
}

__global__ void k_scanB() {
    __shared__ int s[128];
    int t = threadIdx.x;
    int v = (t < NB) ? g_part[t] : 0;
    s[t] = v;
    __syncthreads();
    #pragma unroll
    for (int off = 1; off < 128; off <<= 1) {
        int a = (t >= off) ? s[t - off] : 0;
        __syncthreads();
        s[t] += a;
        __syncthreads();
    }
    if (t < NB) g_part[t] = s[t] - v;
}

__global__ void k_scanC(int n) {
    __shared__ int s[SCAN_CHUNK];
    int t = threadIdx.x;
    int idx = blockIdx.x * SCAN_CHUNK + t;
    int v = (idx < n) ? g_cnt[idx] : 0;
    s[t] = v;
    __syncthreads();
    for (int off = 1; off < SCAN_CHUNK; off <<= 1) {
        int a = (t >= off) ? s[t - off] : 0;
        __syncthreads();
        s[t] += a;
        __syncthreads();
    }
    if (idx < n) g_ptr[idx] = g_part[blockIdx.x] + s[t] - v;
}

// ---------------- CSR build: packed (src, norm) scatter ----------------
__global__ void k_build(const int* __restrict__ row, const int* __restrict__ col,
                        const float* __restrict__ w, int E) {
    int e = blockIdx.x * blockDim.x + threadIdx.x;
    if (e < E) {
        int r = row[e];
        int c = col[e];
        float nv = g_dinv[r] * w[e] * g_dinv[c];
        int pos = g_ptr[c] + atomicAdd(&g_cur[c], 1);
        g_edge[pos] = make_int2(r, __float_as_int(nv));
    }
}

// ---------------- GEMM1: g_hx = x @ W1  via packed fma.rn.f32x2 ----------------
__global__ void __launch_bounds__(128) k_gemm1(const float* __restrict__ x,
                                               const float* __restrict__ W1, int n) {
    __shared__ unsigned long long Ws[DF * HID / 2];  // 32 KB; Ws[c*8+p] packs W1[c*16+2p..2p+1]
    __shared__ float xs[128][17];                    // 8.5 KB, conflict-free
    int t = threadIdx.x;
    int row = blockIdx.x * 128 + t;

    const unsigned long long* Wg = (const unsigned long long*)W1;
    for (int i = t; i < DF * HID / 2; i += 128) Ws[i] = Wg[i];

    unsigned long long acc[8];
    #pragma unroll
    for (int p = 0; p < 8; p++) acc[p] = 0ULL;

    for (int jb = 0; jb < DF; jb += 16) {
        __syncthreads();
        // load 128 rows x 16 cols: each thread does 4 float4 loads, scalar STS
        #pragma unroll
        for (int i = 0; i < 4; i++) {
            int idx = i * 128 + t;           // float4 index in tile
            int r = idx >> 2, c4 = idx & 3;
            int gr = blockIdx.x * 128 + r;
            float4 v = (gr < n) ? ((const float4*)&x[gr * DF + jb])[c4]
                                : make_float4(0.f, 0.f, 0.f, 0.f);
            xs[r][c4 * 4 + 0] = v.x;
            xs[r][c4 * 4 + 1] = v.y;
            xs[r][c4 * 4 + 2] = v.z;
            xs[r][c4 * 4 + 3] = v.w;
        }
        __syncthreads();
        #pragma unroll
        for (int c = 0; c < 16; c++) {
            float xv = xs[t][c];
            unsigned long long xx;
            asm("mov.b64 %0, {%1, %1};" : "=l"(xx) : "f"(xv));
            const ulonglong2* wp = (const ulonglong2*)&Ws[(jb + c) * 8];
            ulonglong2 w01 = wp[0], w23 = wp[1];
            FMA2(acc[0], xx, w01.x);
            FMA2(acc[1], xx, w01.y);
            FMA2(acc[2], xx, w23.x);
            FMA2(acc[3], xx, w23.y);
            ulonglong2 w45 = wp[2], w67 = wp[3];
            FMA2(acc[4], xx, w45.x);
            FMA2(acc[5], xx, w45.y);
            FMA2(acc[6], xx, w67.x);
            FMA2(acc[7], xx, w67.y);
        }
    }
    if (row < n) {
        ulonglong2* o = (ulonglong2*)&g_hx[row * HID];
        o[0] = make_ulonglong2(acc[0], acc[1]);
        o[1] = make_ulonglong2(acc[2], acc[3]);
        o[2] = make_ulonglong2(acc[4], acc[5]);
        o[3] = make_ulonglong2(acc[6], acc[7]);
    }
}

// ---------------- agg phase 1: g_h1 = relu(A_hat @ g_hx + b1) ----------------
__global__ void k_agg1(const float* __restrict__ bias, int n) {
    const float4* in = (const float4*)g_hx;
    int node = (blockIdx.x * blockDim.x + threadIdx.x) >> 5;
    int lane = threadIdx.x & 31;
    if (node >= n) return;

    int q  = lane & 3;
    int es = lane >> 2;
    int start = g_ptr[node];
    int end   = start + g_cnt[node];

    float4 acc = make_float4(0.f, 0.f, 0.f, 0.f);
    for (int e = start + es; e < end; e += 8) {
        int2  ev  = __ldg(&g_edge[e]);
        float nv  = __int_as_float(ev.y);
        float4 v  = in[ev.x * 4 + q];
        acc.x += nv * v.x; acc.y += nv * v.y; acc.z += nv * v.z; acc.w += nv * v.w;
    }
    #pragma unroll
    for (int off = 4; off < 32; off <<= 1) {
        acc.x += __shfl_down_sync(0xffffffffu, acc.x, off);
        acc.y += __shfl_down_sync(0xffffffffu, acc.y, off);
        acc.z += __shfl_down_sync(0xffffffffu, acc.z, off);
        acc.w += __shfl_down_sync(0xffffffffu, acc.w, off);
    }
    if (lane < 4) {
        float d  = g_dinv[node];
        float d2 = d * d;
        float4 sv = in[node * 4 + lane];
        acc.x += d2 * sv.x; acc.y += d2 * sv.y; acc.z += d2 * sv.z; acc.w += d2 * sv.w;
        float4 b = ((const float4*)bias)[lane];
        acc.x = fmaxf(acc.x + b.x, 0.f);
        acc.y = fmaxf(acc.y + b.y, 0.f);
        acc.z = fmaxf(acc.z + b.z, 0.f);
        acc.w = fmaxf(acc.w + b.w, 0.f);
        ((float4*)g_h1)[node * 4 + lane] = acc;
    }
}

// ---------------- agg phase 2 fused with output GEMM ----------------
// out[node] = (A_hat @ g_h1)[node] @ W2 + b2
__global__ void k_agg2_out(float* __restrict__ out, const float* __restrict__ W2,
                           const float* __restrict__ b2, int n) {
    __shared__ float W2s[HID * NC];   // 2.5 KB, layout [h][c]
    __shared__ float b2s[NC];
    int tid = threadIdx.x;
    for (int i = tid; i < HID * NC; i += blockDim.x) W2s[i] = W2[i];
    if (tid < NC) b2s[tid] = b2[tid];
    __syncthreads();

    const float4* in = (const float4*)g_h1;
    int node = (blockIdx.x * blockDim.x + tid) >> 5;
    int lane = tid & 31;
    if (node >= n) return;

    int q  = lane & 3;
    int es = lane >> 2;
    int start = g_ptr[node];
    int end   = start + g_cnt[node];

    float4 acc = make_float4(0.f, 0.f, 0.f, 0.f);
    for (int e = start + es; e < end; e += 8) {
        int2  ev  = __ldg(&g_edge[e]);
        float nv  = __int_as_float(ev.y);
        float4 v  = in[ev.x * 4 + q];
        acc.x += nv * v.x; acc.y += nv * v.y; acc.z += nv * v.z; acc.w += nv * v.w;
    }
    #pragma unroll
    for (int off = 4; off < 32; off <<= 1) {
        acc.x += __shfl_down_sync(0xffffffffu, acc.x, off);
        acc.y += __shfl_down_sync(0xffffffffu, acc.y, off);
        acc.z += __shfl_down_sync(0xffffffffu, acc.z, off);
        acc.w += __shfl_down_sync(0xffffffffu, acc.w, off);
    }
    if (lane < 4) {
        float d  = g_dinv[node];
        float d2 = d * d;
        float4 sv = in[node * 4 + lane];
        acc.x += d2 * sv.x; acc.y += d2 * sv.y; acc.z += d2 * sv.z; acc.w += d2 * sv.w;
    }
    // broadcast the 16 hidden values (lanes 0..3 hold float4 each) to all lanes
    float h[16];
    #pragma unroll
    for (int s = 0; s < 4; s++) {
        h[4 * s + 0] = __shfl_sync(0xffffffffu, acc.x, s);
        h[4 * s + 1] = __shfl_sync(0xffffffffu, acc.y, s);
        h[4 * s + 2] = __shfl_sync(0xffffffffu, acc.z, s);
        h[4 * s + 3] = __shfl_sync(0xffffffffu, acc.w, s);
    }
    // lanes 0..19 each compute 2 classes
    if (lane < NC / 2) {
        int c = 2 * lane;
        float s0 = b2s[c], s1 = b2s[c + 1];
        #pragma unroll
        for (int k = 0; k < HID; k++) {
            s0 += h[k] * W2s[k * NC + c];
            s1 += h[k] * W2s[k * NC + c + 1];
        }
        ((float2*)&out[node * NC])[lane] = make_float2(s0, s1);
    }
}

// ---------------- launch ----------------
extern "C" void kernel_launch(void* const* d_in, const int* in_sizes, int n_in,
                              void* d_out, int out_size) {
    const float* x  = (const float*)d_in[0];
    const int*   ei = (const int*)  d_in[1];
    const float* ew = (const float*)d_in[2];
    const float* W1 = (const float*)d_in[3];
    const float* b1 = (const float*)d_in[4];
    const float* W2 = (const float*)d_in[5];
    const float* b2 = (const float*)d_in[6];

    int E = in_sizes[2];
    int n = in_sizes[0] / DF;
    const int* rowp = ei;
    const int* colp = ei + E;

    int nb256 = (n + 255) / 256;
    int eb256 = (E + 255) / 256;

    k_init  <<<nb256, 256>>>(n);
    k_pass1 <<<eb256, 256>>>(colp, ew, E);
    k_scanA <<<NB, 256>>>(n);
    k_scanB <<<1, 128>>>();
    k_scanC <<<NB, SCAN_CHUNK>>>(n);
    k_build <<<eb256, 256>>>(rowp, colp, ew, E);

    k_gemm1 <<<(n + 127) / 128, 128>>>(x, W1, n);

    long wthreads = (long)n * 32;
    int aggblocks = (int)((wthreads + 255) / 256);
    k_agg1    <<<aggblocks, 256>>>(b1, n);
    k_agg2_out<<<aggblocks, 256>>>((float*)d_out, W2, b2, n);
}